// round 15
// baseline (speedup 1.0000x reference)
#include <cuda_runtime.h>

// Problem shape (fixed by the dataset)
#define BB 8
#define SS 128
#define RR 192
#define CC 192
#define NX (CC / 4)   // 48 float4 segments per row

#define RTILES (RR / 4)                // 48
#define STILES (SS / 2)                // 64 s-tiles (2 planes each)
#define NCOLS (BB * RTILES)            // 384 (b, r-tile) columns
#define NTILES (NCOLS * STILES)        // 24576
#define OCC 6
#define NBLOCKS (148 * OCC)            // 888 persistent CTAs, single wave

// SPACING = (2.0, 1.5, 1.5) along (S, R, C)
#define INV2DX 0.25f
#define INV2DY 0.33333333333333333f
#define INV2DZ 0.33333333333333333f
#define INVDX2 0.25f
#define INVDY2 0.44444444444444444f
#define INVDZ2 0.44444444444444444f

__device__ __forceinline__ int clamp_i(int v, int lo, int hi) {
    return min(max(v, lo), hi);
}

// Compute one output float4 for one plane (scalar math — R4 proven path).
__device__ __forceinline__ float4 plane_out(const float4 c,
                                            const float4 xm, const float4 xp,
                                            const float4 ym, const float4 yp,
                                            const float left, const float right,
                                            const float4 d,
                                            const bool lo, const bool hi)
{
    const float ca[4]  = {c.x,  c.y,  c.z,  c.w};
    const float xma[4] = {xm.x, xm.y, xm.z, xm.w};
    const float xpa[4] = {xp.x, xp.y, xp.z, xp.w};
    const float yma[4] = {ym.x, ym.y, ym.z, ym.w};
    const float ypa[4] = {yp.x, yp.y, yp.z, yp.w};
    const float zma[4] = {left, c.x,  c.y,  c.z};
    const float zpa[4] = {c.y,  c.z,  c.w,  right};
    const float da[4]  = {d.x,  d.y,  d.z,  d.w};

    float Fxy[4], Gxy[4], oa[4];
    #pragma unroll
    for (int j = 0; j < 4; ++j) {
        const float gx = (xpa[j] - xma[j]) * INV2DX;
        const float gy = (ypa[j] - yma[j]) * INV2DY;
        Fxy[j] = gx * gx + gy * gy;
        Gxy[j] = (xpa[j] - 2.0f * ca[j] + xma[j]) * INVDX2
               + (ypa[j] - 2.0f * ca[j] + yma[j]) * INVDY2;
        const float gz = (zpa[j] - zma[j]) * INV2DZ;
        const float Gz = (zpa[j] - 2.0f * ca[j] + zma[j]) * INVDZ2;
        oa[j] = -0.5f * (Fxy[j] + gz * gz) - da[j] * (Gxy[j] + Gz);
    }

    if (lo) {
        // k=1 (comp 1): zm tap is Q(0)=P[col 1]=c.y
        const float gz1 = (c.z - c.y) * INV2DZ;
        const float Gz1 = (c.z - c.y) * INVDZ2;
        oa[1] = -0.5f * (Fxy[1] + gz1 * gz1) - da[1] * (Gxy[1] + Gz1);
        // k=0 (comp 0): all column taps clamp to col 1
        oa[0] = -0.5f * Fxy[1] - da[0] * Gxy[1];
    }
    if (hi) {
        // k=190 (comp 2): zp tap is Q(191)=P[col 190]=c.z
        const float gz2 = (c.z - c.y) * INV2DZ;
        const float Gz2 = (c.y - c.z) * INVDZ2;
        oa[2] = -0.5f * (Fxy[2] + gz2 * gz2) - da[2] * (Gxy[2] + Gz2);
        // k=191 (comp 3): all column taps clamp to col 190
        oa[3] = -0.5f * Fxy[2] - da[3] * Gxy[2];
    }

    return make_float4(oa[0], oa[1], oa[2], oa[3]);
}

__global__ __launch_bounds__(192, OCC)
void flowp_kernel_range(const float* __restrict__ P,
                        const float* __restrict__ D,
                        float* __restrict__ out)
{
    const int tx = threadIdx.x;          // 0..47 : float4 index along C
    const int ty = threadIdx.y;          // 0..3  : r within tile
    const int k0 = tx * 4;
    const bool lo = (tx == 0);
    const bool hi = (tx == NX - 1);

    // Column edge offsets (constant across tiles)
    const int kl = lo ? k0 : k0 - 1;
    const int kr = hi ? CC - 1 : k0 + 4;

    // Contiguous tile range for this CTA, tiles ordered column-major
    // (s fastest): successive tiles walk s within one (b, r-tile) column,
    // so L1 reuses the shared planes between consecutive s-tiles.
    const int Tbeg = (int)(((long long)blockIdx.x * NTILES) / NBLOCKS);
    const int Tend = (int)(((long long)(blockIdx.x + 1) * NTILES) / NBLOCKS);

    #pragma unroll 1
    for (int T = Tbeg; T < Tend; ++T) {
        const int st  = T & (STILES - 1);    // s fastest
        const int col = T >> 6;              // / STILES (=64)
        const int rb  = col % RTILES;
        const int b   = col / RTILES;

        const int r  = rb * 4 + ty;
        const int s0 = st * 2;

        const int i0 = clamp_i(s0 - 1, 1, SS - 2);
        const int i1 = clamp_i(s0,     1, SS - 2);
        const int i2 = clamp_i(s0 + 1, 1, SS - 2);
        const int i3 = clamp_i(s0 + 2, 1, SS - 2);

        const int cr = clamp_i(r,     1, RR - 2);
        const int rm = clamp_i(r - 1, 1, RR - 2);
        const int rp = clamp_i(r + 1, 1, RR - 2);

        const long long base = (long long)b * (SS * RR * CC);
        const float* Pb = P + base;

        const int rowA   = (i0 * RR + cr) * CC;
        const int rowC1  = (i1 * RR + cr) * CC;
        const int rowC2  = (i2 * RR + cr) * CC;
        const int rowBp  = (i3 * RR + cr) * CC;
        const int rowY1m = (i1 * RR + rm) * CC;
        const int rowY1p = (i1 * RR + rp) * CC;
        const int rowY2m = (i2 * RR + rm) * CC;
        const int rowY2p = (i2 * RR + rp) * CC;

        const float4 A   = __ldg((const float4*)(Pb + rowA   + k0));
        const float4 C1  = __ldg((const float4*)(Pb + rowC1  + k0));
        const float4 C2  = __ldg((const float4*)(Pb + rowC2  + k0));
        const float4 Bp  = __ldg((const float4*)(Pb + rowBp  + k0));
        const float4 Y1m = __ldg((const float4*)(Pb + rowY1m + k0));
        const float4 Y1p = __ldg((const float4*)(Pb + rowY1p + k0));
        const float4 Y2m = __ldg((const float4*)(Pb + rowY2m + k0));
        const float4 Y2p = __ldg((const float4*)(Pb + rowY2p + k0));

        const float l1 = __ldg(Pb + rowC1 + kl);
        const float r1 = __ldg(Pb + rowC1 + kr);
        const float l2 = __ldg(Pb + rowC2 + kl);
        const float r2 = __ldg(Pb + rowC2 + kr);

        const long long idx0 = base + ((long long)(s0 * RR + r)) * CC + k0;
        const long long idx1 = idx0 + (long long)RR * CC;
        const float4 d0 = __ldg((const float4*)(D + idx0));
        const float4 d1 = __ldg((const float4*)(D + idx1));

        const float4 o0 = plane_out(C1, A,  C2, Y1m, Y1p, l1, r1, d0, lo, hi);
        const float4 o1 = plane_out(C2, C1, Bp, Y2m, Y2p, l2, r2, d1, lo, hi);

        *((float4*)(out + idx0)) = o0;
        *((float4*)(out + idx1)) = o1;
    }
}

extern "C" void kernel_launch(void* const* d_in, const int* in_sizes, int n_in,
                              void* d_out, int out_size)
{
    // inputs (metadata order): t (unused), batch_P, D
    const float* P = (const float*)d_in[1];
    const float* D = (const float*)d_in[2];
    float* out = (float*)d_out;

    dim3 grid(NBLOCKS);
    dim3 block(NX, 4);   // 192 threads
    flowp_kernel_range<<<grid, block>>>(P, D, out);
}

// round 16
// speedup vs baseline: 1.0989x; 1.0989x over previous
#include <cuda_runtime.h>
#include <cstdint>

// Problem shape (fixed by the dataset)
#define BB 8
#define SS 128
#define RR 192
#define CC 192
#define NX (CC / 4)   // 48 float4 segments per row

#define RTILES (RR / 4)                // 48
#define STILES (SS / 2)                // 64 s-tiles (2 planes each)
#define NCOLS (BB * RTILES)            // 384 (b, r-tile) columns
#define NCHUNKS 2
#define SCHUNK (STILES / NCHUNKS)      // 32 s-tiles per CTA
#define NBLOCKS (NCOLS * NCHUNKS)      // 768 CTAs, all resident

#define NRING 6                        // smem plane ring slots
#define ROWS_PB 6                      // 4 center rows + 2 halo
#define PLANE_F (ROWS_PB * CC)         // 1152 floats per plane buffer
#define PLANE_B (PLANE_F * 4)          // 4608 bytes

// SPACING = (2.0, 1.5, 1.5) along (S, R, C)
#define INV2DX 0.25f
#define INV2DY 0.33333333333333333f
#define INV2DZ 0.33333333333333333f
#define INVDX2 0.25f
#define INVDY2 0.44444444444444444f
#define INVDZ2 0.44444444444444444f

__device__ __forceinline__ int clamp_i(int v, int lo, int hi) {
    return min(max(v, lo), hi);
}

__device__ __forceinline__ void cpa16(uint32_t dst, const float* src) {
    asm volatile("cp.async.ca.shared.global [%0], [%1], 16;" :: "r"(dst), "l"(src));
}

// Compute one output float4 for one plane (scalar math — R4 proven path).
__device__ __forceinline__ float4 plane_out(const float4 c,
                                            const float4 xm, const float4 xp,
                                            const float4 ym, const float4 yp,
                                            const float left, const float right,
                                            const float4 d,
                                            const bool lo, const bool hi)
{
    const float ca[4]  = {c.x,  c.y,  c.z,  c.w};
    const float xma[4] = {xm.x, xm.y, xm.z, xm.w};
    const float xpa[4] = {xp.x, xp.y, xp.z, xp.w};
    const float yma[4] = {ym.x, ym.y, ym.z, ym.w};
    const float ypa[4] = {yp.x, yp.y, yp.z, yp.w};
    const float zma[4] = {left, c.x,  c.y,  c.z};
    const float zpa[4] = {c.y,  c.z,  c.w,  right};
    const float da[4]  = {d.x,  d.y,  d.z,  d.w};

    float Fxy[4], Gxy[4], oa[4];
    #pragma unroll
    for (int j = 0; j < 4; ++j) {
        const float gx = (xpa[j] - xma[j]) * INV2DX;
        const float gy = (ypa[j] - yma[j]) * INV2DY;
        Fxy[j] = gx * gx + gy * gy;
        Gxy[j] = (xpa[j] - 2.0f * ca[j] + xma[j]) * INVDX2
               + (ypa[j] - 2.0f * ca[j] + yma[j]) * INVDY2;
        const float gz = (zpa[j] - zma[j]) * INV2DZ;
        const float Gz = (zpa[j] - 2.0f * ca[j] + zma[j]) * INVDZ2;
        oa[j] = -0.5f * (Fxy[j] + gz * gz) - da[j] * (Gxy[j] + Gz);
    }

    if (lo) {
        const float gz1 = (c.z - c.y) * INV2DZ;
        const float Gz1 = (c.z - c.y) * INVDZ2;
        oa[1] = -0.5f * (Fxy[1] + gz1 * gz1) - da[1] * (Gxy[1] + Gz1);
        oa[0] = -0.5f * Fxy[1] - da[0] * Gxy[1];
    }
    if (hi) {
        const float gz2 = (c.z - c.y) * INV2DZ;
        const float Gz2 = (c.y - c.z) * INVDZ2;
        oa[2] = -0.5f * (Fxy[2] + gz2 * gz2) - da[2] * (Gxy[2] + Gz2);
        oa[3] = -0.5f * Fxy[2] - da[3] * Gxy[2];
    }

    return make_float4(oa[0], oa[1], oa[2], oa[3]);
}

__global__ __launch_bounds__(192, 6)
void flowp_kernel_cpa(const float* __restrict__ P,
                      const float* __restrict__ D,
                      float* __restrict__ out)
{
    __shared__ __align__(16) float smP[NRING * PLANE_F];   // 27648 B

    const int tx  = threadIdx.x;         // 0..47
    const int ty  = threadIdx.y;         // 0..3
    const int tid = tx + NX * ty;        // 0..191
    const int k0  = tx * 4;
    const bool lo = (tx == 0);
    const bool hi = (tx == NX - 1);
    const int kl = lo ? k0 : k0 - 1;
    const int kr = hi ? CC - 1 : k0 + 4;

    // col fastest => rb-adjacent CTAs run concurrently (preserves L2 halo sharing)
    const int col   = blockIdx.x % NCOLS;
    const int chunk = blockIdx.x / NCOLS;
    const int rb    = col % RTILES;
    const int b     = col / RTILES;
    const int r0    = rb * 4;
    const int s0f   = chunk * SCHUNK * 2;   // first plane of first tile

    const long long base = (long long)b * (SS * RR * CC);
    const float* Pb = P + base;

    const uint32_t smb = (uint32_t)__cvta_generic_to_shared(smP);

    // async-copy element assignment: plane = 288 float4; thread does e0=tid,
    // e1=tid+192 (threads 0..95 only)
    const int e0row = tid / NX;
    const int e0c   = (tid % NX) * 4;
    const int e1row = (tid + 192) / NX;
    const int e1c   = ((tid + 192) % NX) * 4;
    const int g0 = clamp_i(r0 - 1 + e0row, 1, RR - 2);   // global row for e0
    const int g1 = clamp_i(r0 - 1 + e1row, 1, RR - 2);

    auto issue_plane = [&](int p) {
        const int i    = clamp_i(p, 1, SS - 2);
        const int slot = (p + 1) % NRING;
        const float* sp = Pb + i * (RR * CC);
        cpa16(smb + slot * PLANE_B + (e0row * CC + e0c) * 4, sp + g0 * CC + e0c);
        if (tid < 96)
            cpa16(smb + slot * PLANE_B + (e1row * CC + e1c) * 4, sp + g1 * CC + e1c);
    };

    // Prologue: planes s0f-1 .. s0f+2 (two commit groups)
    issue_plane(s0f - 1);
    issue_plane(s0f);
    asm volatile("cp.async.commit_group;" ::: "memory");
    issue_plane(s0f + 1);
    issue_plane(s0f + 2);
    asm volatile("cp.async.commit_group;" ::: "memory");

    #pragma unroll 1
    for (int j = 0; j < SCHUNK; ++j) {
        const int s0 = s0f + 2 * j;

        // all planes up to s0+2 ready
        asm volatile("cp.async.wait_group 0;" ::: "memory");
        __syncthreads();   // data visible CTA-wide; previous readers done

        // prefetch planes for the NEXT tile (slots disjoint from this tile's)
        if (j < SCHUNK - 1) {
            issue_plane(s0 + 3);
            issue_plane(s0 + 4);
            asm volatile("cp.async.commit_group;" ::: "memory");
        }

        // smem row pointers (slot(p) = (p+1)%NRING)
        const float* pA  = smP + ((s0    ) % NRING) * PLANE_F + (ty + 1) * CC;
        const float* pC1 = smP + ((s0 + 1) % NRING) * PLANE_F + (ty + 1) * CC;
        const float* pC2 = smP + ((s0 + 2) % NRING) * PLANE_F + (ty + 1) * CC;
        const float* pBp = smP + ((s0 + 3) % NRING) * PLANE_F + (ty + 1) * CC;
        const float* pY1m = pC1 - CC;
        const float* pY1p = pC1 + CC;
        const float* pY2m = pC2 - CC;
        const float* pY2p = pC2 + CC;

        const float4 A   = *(const float4*)(pA   + k0);
        const float4 C1  = *(const float4*)(pC1  + k0);
        const float4 C2  = *(const float4*)(pC2  + k0);
        const float4 Bp  = *(const float4*)(pBp  + k0);
        const float4 Y1m = *(const float4*)(pY1m + k0);
        const float4 Y1p = *(const float4*)(pY1p + k0);
        const float4 Y2m = *(const float4*)(pY2m + k0);
        const float4 Y2p = *(const float4*)(pY2p + k0);

        const float l1 = pC1[kl];
        const float r1 = pC1[kr];
        const float l2 = pC2[kl];
        const float r2 = pC2[kr];

        const long long idx0 = base + ((long long)(s0 * RR + (r0 + ty))) * CC + k0;
        const long long idx1 = idx0 + (long long)RR * CC;
        const float4 d0 = __ldg((const float4*)(D + idx0));
        const float4 d1 = __ldg((const float4*)(D + idx1));

        const float4 o0 = plane_out(C1, A,  C2, Y1m, Y1p, l1, r1, d0, lo, hi);
        const float4 o1 = plane_out(C2, C1, Bp, Y2m, Y2p, l2, r2, d1, lo, hi);

        *((float4*)(out + idx0)) = o0;
        *((float4*)(out + idx1)) = o1;

        __syncthreads();   // protect ring slots from next iteration's overwrite
    }
}

extern "C" void kernel_launch(void* const* d_in, const int* in_sizes, int n_in,
                              void* d_out, int out_size)
{
    // inputs (metadata order): t (unused), batch_P, D
    const float* P = (const float*)d_in[1];
    const float* D = (const float*)d_in[2];
    float* out = (float*)d_out;

    dim3 grid(NBLOCKS);
    dim3 block(NX, 4);   // 192 threads
    flowp_kernel_cpa<<<grid, block>>>(P, D, out);
}